// round 12
// baseline (speedup 1.0000x reference)
#include <cuda_runtime.h>
#include <cuda_bf16.h>

// R11: split kernels.
//  A: conv1(3->16,3x3,pad1)+exact GELU -> g_h[b][ci][y][x]  (unchanged from R10)
//  B: smem h-tile (aligned float4 copy + 1-col halo arrays) -> conv2 per
//     nonzero tap (R7 proven 2px/thread stage-2) -> bilinear sampling.

#define HH 512
#define WW 512
#define HWS (HH * WW)
#define BMAX 8

__constant__ float c_w1[432];    // (16,3,3,3)
__constant__ float c_b1[16];
__constant__ float c_w2[2592];   // (18,16,3,3)
__constant__ float c_b2[18];
__constant__ float c_wt[9];

// intermediate h, channel-plane major: [b][ci][y][x]
__device__ float g_h[BMAX * 16 * HWS];

// exact GELU via Abramowitz-Stegun 7.1.26 erf (|abs err| <= 1.5e-7)
__device__ __forceinline__ float gelu_fast(float x) {
    float z = 0.70710678118f * x;
    float a = fabsf(z);
    float t = __fdividef(1.0f, fmaf(0.3275911f, a, 1.0f));
    float p = fmaf(1.061405429f, t, -1.453152027f);
    p = fmaf(p, t, 1.421413741f);
    p = fmaf(p, t, -0.284496736f);
    p = fmaf(p, t, 0.254829592f);
    p = p * t;
    float e = __expf(-a * a);
    float erfa = fmaf(-p, e, 1.0f);
    float erfz = copysignf(erfa, z);
    return x * (0.5f * (1.0f + erfz));
}

// ---------------- Kernel A: conv1 + GELU, 2 px/thread, 1 row/block ----------
__global__ __launch_bounds__(256)
void conv1_gelu_kernel(const float* __restrict__ wind,
                       const float* __restrict__ topo) {
    const int b   = blockIdx.z;
    const int y   = blockIdx.y;
    const int gx0 = threadIdx.x * 2;          // 0..510

    const float* src[3];
    src[0] = wind + (size_t)b * 2 * HWS;
    src[1] = src[0] + HWS;
    src[2] = topo + (size_t)b * HWS;

    const bool ml = gx0 > 0;
    const bool mr = gx0 + 2 < WW;
    const int  xl = max(gx0 - 1, 0);
    const int  xr = min(gx0 + 2, WW - 1);

    float in_reg[3][3][4];
    #pragma unroll
    for (int c = 0; c < 3; c++) {
        #pragma unroll
        for (int r = 0; r < 3; r++) {
            int ry = y - 1 + r;
            bool rok = (unsigned)ry < HH;
            const float* row = src[c] + min(max(ry, 0), HH - 1) * WW;
            float a = row[xl];
            float2 m = *(const float2*)&row[gx0];
            float d = row[xr];
            in_reg[c][r][0] = (rok && ml) ? a   : 0.f;
            in_reg[c][r][1] = rok         ? m.x : 0.f;
            in_reg[c][r][2] = rok         ? m.y : 0.f;
            in_reg[c][r][3] = (rok && mr) ? d   : 0.f;
        }
    }

    float* hb = g_h + (size_t)b * 16 * HWS + (size_t)y * WW + gx0;
    #pragma unroll
    for (int o = 0; o < 16; o++) {
        float a0 = c_b1[o], a1 = a0;
        #pragma unroll
        for (int c = 0; c < 3; c++)
            #pragma unroll
            for (int r = 0; r < 3; r++)
                #pragma unroll
                for (int kx = 0; kx < 3; kx++) {
                    const float w = c_w1[o * 27 + (c * 3 + r) * 3 + kx];
                    a0 = fmaf(in_reg[c][r][kx],     w, a0);
                    a1 = fmaf(in_reg[c][r][kx + 1], w, a1);
                }
        *(float2*)&hb[(size_t)o * HWS] = make_float2(gelu_fast(a0), gelu_fast(a1));
    }
}

// ---------------- Kernel B: smem tile + conv2 per tap + bilinear ------------
__global__ __launch_bounds__(256, 4)
void deform_kernel(const float* __restrict__ pm25,
                   float* __restrict__ out) {
    __shared__ float s_h[16][18][36];   // cols tx0..tx0+31 at [0..31]; 41472 B
    __shared__ float s_hL[16][18];      // col tx0-1
    __shared__ float s_hR[16][18];      // col tx0+32

    const int tid = threadIdx.x;
    const int b   = blockIdx.z;
    const int ty0 = blockIdx.y * 16;
    const int tx0 = blockIdx.x * 32;
    const float* hb = g_h + (size_t)b * 16 * HWS;

    // ---- main tile: 288 rows x 8 float4 = 2304 items, 9 iters/thread ----
    for (int j = tid; j < 2304; j += 256) {
        int row = j >> 3;                 // 0..287 = ci*18+hy
        int q   = j & 7;
        int ci  = row / 18;
        int hy  = row - ci * 18;
        int gy  = ty0 - 1 + hy;
        float4 v = make_float4(0.f, 0.f, 0.f, 0.f);
        if ((unsigned)gy < HH)
            v = *(const float4*)(hb + (size_t)ci * HWS + (size_t)gy * WW + tx0 + q * 4);
        *(float4*)&s_h[ci][hy][q * 4] = v;
    }
    // ---- halo columns tx0-1 / tx0+32 : 576 scalars ----
    for (int j = tid; j < 576; j += 256) {
        int side = (j >= 288);
        int r    = j - side * 288;
        int ci   = r / 18;
        int hy   = r - ci * 18;
        int gy   = ty0 - 1 + hy;
        int gx   = side ? (tx0 + 32) : (tx0 - 1);
        float v = 0.f;
        if ((unsigned)gy < HH && (unsigned)gx < WW)
            v = hb[(size_t)ci * HWS + (size_t)gy * WW + gx];
        if (side) s_hR[ci][hy] = v; else s_hL[ci][hy] = v;
    }
    __syncthreads();

    // ---- stage 2: 2 horizontal outputs per thread (R7 pattern) ----
    const int py  = tid >> 4;            // 0..15
    const int px2 = (tid & 15) * 2;      // 0..30
    const int gy  = ty0 + py;
    const int gx0 = tx0 + px2;
    const float* pimg = pm25 + (size_t)b * HWS;
    const bool atL = (px2 == 0);
    const bool atR = (px2 == 30);
    const int  iL  = atL ? 0 : px2 - 1;  // clamped in-bounds index
    const int  iR  = atR ? 31 : px2 + 2;

    float out0 = 0.f, out1 = 0.f;
    #pragma unroll 1
    for (int k = 0; k < 9; k++) {
        float wk = c_wt[k];
        if (wk == 0.f) continue;         // warp-uniform skip

        float dy0 = c_b2[2 * k],     dy1 = dy0;
        float dx0 = c_b2[2 * k + 1], dx1 = dx0;
        const int wbase_y = (2 * k) * 144;
        const int wbase_x = (2 * k + 1) * 144;
        #pragma unroll
        for (int ky = 0; ky < 3; ky++) {
            #pragma unroll
            for (int ci = 0; ci < 16; ci++) {
                const float* m = &s_h[ci][py + ky][0];
                float2 md = *(const float2*)&m[px2];       // gx0, gx0+1
                float vL = m[iL];
                float vR = m[iR];
                float in0 = atL ? s_hL[ci][py + ky] : vL;  // gx0-1
                float in3 = atR ? s_hR[ci][py + ky] : vR;  // gx0+2
                const int wi = ci * 9 + ky * 3;
                float wy0 = c_w2[wbase_y + wi + 0];
                float wy1 = c_w2[wbase_y + wi + 1];
                float wy2 = c_w2[wbase_y + wi + 2];
                float wx0 = c_w2[wbase_x + wi + 0];
                float wx1 = c_w2[wbase_x + wi + 1];
                float wx2 = c_w2[wbase_x + wi + 2];
                dy0 = fmaf(in0,  wy0, dy0); dy0 = fmaf(md.x, wy1, dy0); dy0 = fmaf(md.y, wy2, dy0);
                dy1 = fmaf(md.x, wy0, dy1); dy1 = fmaf(md.y, wy1, dy1); dy1 = fmaf(in3,  wy2, dy1);
                dx0 = fmaf(in0,  wx0, dx0); dx0 = fmaf(md.x, wx1, dx0); dx0 = fmaf(md.y, wx2, dx0);
                dx1 = fmaf(md.x, wx0, dx1); dx1 = fmaf(md.y, wx1, dx1); dx1 = fmaf(in3,  wx2, dx1);
            }
        }

        const float kyo = (float)(k / 3 - 1);
        const float kxo = (float)(k % 3 - 1);
        #pragma unroll
        for (int px = 0; px < 2; px++) {
            float dyv = px ? dy1 : dy0;
            float dxv = px ? dx1 : dx0;
            float py_ = (float)gy + kyo + dyv;
            float px_ = (float)(gx0 + px) + kxo + dxv;
            float y0f = floorf(py_), x0f = floorf(px_);
            float wy = py_ - y0f, wx = px_ - x0f;
            int y0 = (int)y0f, x0 = (int)x0f;
            int y1 = y0 + 1,   x1 = x0 + 1;
            bool vy0 = (unsigned)y0 < HH, vy1 = (unsigned)y1 < HH;
            bool vx0 = (unsigned)x0 < WW, vx1 = (unsigned)x1 < WW;
            int yc0 = min(max(y0, 0), HH - 1), yc1 = min(max(y1, 0), HH - 1);
            int xc0 = min(max(x0, 0), WW - 1), xc1 = min(max(x1, 0), WW - 1);
            const float* r0 = pimg + yc0 * WW;
            const float* r1 = pimg + yc1 * WW;
            float v00 = (vy0 && vx0) ? r0[xc0] : 0.f;
            float v01 = (vy0 && vx1) ? r0[xc1] : 0.f;
            float v10 = (vy1 && vx0) ? r1[xc0] : 0.f;
            float v11 = (vy1 && vx1) ? r1[xc1] : 0.f;
            float samp = (1.f - wy) * (1.f - wx) * v00
                       + (1.f - wy) * wx         * v01
                       + wy         * (1.f - wx) * v10
                       + wy         * wx         * v11;
            if (px) out1 = fmaf(samp, wk, out1);
            else    out0 = fmaf(samp, wk, out0);
        }
    }

    *(float2*)&out[(size_t)b * HWS + (size_t)gy * WW + gx0] = make_float2(out0, out1);
}

extern "C" void kernel_launch(void* const* d_in, const int* in_sizes, int n_in,
                              void* d_out, int out_size) {
    const float* pm25 = (const float*)d_in[0];
    const float* wind = (const float*)d_in[1];
    const float* topo = (const float*)d_in[2];

    cudaMemcpyToSymbolAsync(c_w1, d_in[3], 432  * sizeof(float), 0, cudaMemcpyDeviceToDevice);
    cudaMemcpyToSymbolAsync(c_b1, d_in[4], 16   * sizeof(float), 0, cudaMemcpyDeviceToDevice);
    cudaMemcpyToSymbolAsync(c_w2, d_in[5], 2592 * sizeof(float), 0, cudaMemcpyDeviceToDevice);
    cudaMemcpyToSymbolAsync(c_b2, d_in[6], 18   * sizeof(float), 0, cudaMemcpyDeviceToDevice);
    cudaMemcpyToSymbolAsync(c_wt, d_in[7], 9    * sizeof(float), 0, cudaMemcpyDeviceToDevice);

    float* out = (float*)d_out;
    int B = in_sizes[0] / (HH * WW);

    dim3 gridA(1, HH, B);          // one 512-px row per block, 2 px/thread
    conv1_gelu_kernel<<<gridA, 256>>>(wind, topo);

    dim3 gridB(WW / 32, HH / 16, B);   // 32x16 tile, 2 px/thread
    deform_kernel<<<gridB, 256>>>(pm25, out);
}

// round 13
// speedup vs baseline: 1.0875x; 1.0875x over previous
#include <cuda_runtime.h>
#include <cuda_bf16.h>

// R13: split kernels.
//  A: conv1(3->16,3x3,pad1)+exact GELU -> g_h[b][ci][y][x]  (unchanged)
//  B: smem h-tile with halo BAKED INTO the index origin (x=0 <-> tx0-1),
//     so stage-2 is R7's exact 2xLDS.64 pattern: no selects, no conflicts.

#define HH 512
#define WW 512
#define HWS (HH * WW)
#define BMAX 8

__constant__ float c_w1[432];    // (16,3,3,3)
__constant__ float c_b1[16];
__constant__ float c_w2[2592];   // (18,16,3,3)
__constant__ float c_b2[18];
__constant__ float c_wt[9];

// intermediate h, channel-plane major: [b][ci][y][x]
__device__ float g_h[BMAX * 16 * HWS];

// exact GELU via Abramowitz-Stegun 7.1.26 erf (|abs err| <= 1.5e-7)
__device__ __forceinline__ float gelu_fast(float x) {
    float z = 0.70710678118f * x;
    float a = fabsf(z);
    float t = __fdividef(1.0f, fmaf(0.3275911f, a, 1.0f));
    float p = fmaf(1.061405429f, t, -1.453152027f);
    p = fmaf(p, t, 1.421413741f);
    p = fmaf(p, t, -0.284496736f);
    p = fmaf(p, t, 0.254829592f);
    p = p * t;
    float e = __expf(-a * a);
    float erfa = fmaf(-p, e, 1.0f);
    float erfz = copysignf(erfa, z);
    return x * (0.5f * (1.0f + erfz));
}

// ---------------- Kernel A: conv1 + GELU, 2 px/thread, 1 row/block ----------
__global__ __launch_bounds__(256)
void conv1_gelu_kernel(const float* __restrict__ wind,
                       const float* __restrict__ topo) {
    const int b   = blockIdx.z;
    const int y   = blockIdx.y;
    const int gx0 = threadIdx.x * 2;          // 0..510

    const float* src[3];
    src[0] = wind + (size_t)b * 2 * HWS;
    src[1] = src[0] + HWS;
    src[2] = topo + (size_t)b * HWS;

    const bool ml = gx0 > 0;
    const bool mr = gx0 + 2 < WW;
    const int  xl = max(gx0 - 1, 0);
    const int  xr = min(gx0 + 2, WW - 1);

    float in_reg[3][3][4];
    #pragma unroll
    for (int c = 0; c < 3; c++) {
        #pragma unroll
        for (int r = 0; r < 3; r++) {
            int ry = y - 1 + r;
            bool rok = (unsigned)ry < HH;
            const float* row = src[c] + min(max(ry, 0), HH - 1) * WW;
            float a = row[xl];
            float2 m = *(const float2*)&row[gx0];
            float d = row[xr];
            in_reg[c][r][0] = (rok && ml) ? a   : 0.f;
            in_reg[c][r][1] = rok         ? m.x : 0.f;
            in_reg[c][r][2] = rok         ? m.y : 0.f;
            in_reg[c][r][3] = (rok && mr) ? d   : 0.f;
        }
    }

    float* hb = g_h + (size_t)b * 16 * HWS + (size_t)y * WW + gx0;
    #pragma unroll
    for (int o = 0; o < 16; o++) {
        float a0 = c_b1[o], a1 = a0;
        #pragma unroll
        for (int c = 0; c < 3; c++)
            #pragma unroll
            for (int r = 0; r < 3; r++)
                #pragma unroll
                for (int kx = 0; kx < 3; kx++) {
                    const float w = c_w1[o * 27 + (c * 3 + r) * 3 + kx];
                    a0 = fmaf(in_reg[c][r][kx],     w, a0);
                    a1 = fmaf(in_reg[c][r][kx + 1], w, a1);
                }
        *(float2*)&hb[(size_t)o * HWS] = make_float2(gelu_fast(a0), gelu_fast(a1));
    }
}

// ---------------- Kernel B: smem tile + conv2 per tap + bilinear ------------
// s_h[ci][hy][x] : x = 0..33 corresponds to global columns tx0-1 .. tx0+32.
__global__ __launch_bounds__(256, 4)
void deform_kernel(const float* __restrict__ pm25,
                   float* __restrict__ out) {
    __shared__ float s_h[16][18][36];   // 41472 B

    const int tid = threadIdx.x;
    const int b   = blockIdx.z;
    const int ty0 = blockIdx.y * 16;
    const int tx0 = blockIdx.x * 32;
    const float* hb = g_h + (size_t)b * 16 * HWS;

    // ---- main tile: per (ci,hy) row, 8 aligned LDG.128 at tx0+4q, each
    // stored as 4 scalar STS into x = 4q+1..4q+4 (odd shift). 2304 items.
    for (int j = tid; j < 2304; j += 256) {
        int row = j >> 3;                 // ci*18 + hy
        int q   = j & 7;
        int ci  = row / 18;
        int hy  = row - ci * 18;
        int gy  = ty0 - 1 + hy;
        float4 v = make_float4(0.f, 0.f, 0.f, 0.f);
        if ((unsigned)gy < HH)
            v = *(const float4*)(hb + (size_t)ci * HWS + (size_t)gy * WW + tx0 + q * 4);
        float* d = &s_h[ci][hy][q * 4 + 1];
        d[0] = v.x; d[1] = v.y; d[2] = v.z; d[3] = v.w;
    }
    // ---- halo columns: x=0 (global tx0-1) and x=33 (global tx0+32) ----
    for (int j = tid; j < 576; j += 256) {
        int side = (j >= 288);
        int r    = j - side * 288;
        int ci   = r / 18;
        int hy   = r - ci * 18;
        int gy   = ty0 - 1 + hy;
        int gx   = side ? (tx0 + 32) : (tx0 - 1);
        float v = 0.f;
        if ((unsigned)gy < HH && (unsigned)gx < WW)
            v = hb[(size_t)ci * HWS + (size_t)gy * WW + gx];
        s_h[ci][hy][side ? 33 : 0] = v;
    }
    __syncthreads();

    // ---- stage 2: R7-exact 2px/thread pattern ----
    const int py  = tid >> 4;            // 0..15
    const int px2 = (tid & 15) * 2;      // 0..30
    const int gy  = ty0 + py;
    const int gx0 = tx0 + px2;
    const float* pimg = pm25 + (size_t)b * HWS;

    float out0 = 0.f, out1 = 0.f;
    #pragma unroll 1
    for (int k = 0; k < 9; k++) {
        float wk = c_wt[k];
        if (wk == 0.f) continue;         // warp-uniform skip

        float dy0 = c_b2[2 * k],     dy1 = dy0;
        float dx0 = c_b2[2 * k + 1], dx1 = dx0;
        const int wbase_y = (2 * k) * 144;
        const int wbase_x = (2 * k + 1) * 144;
        #pragma unroll
        for (int ky = 0; ky < 3; ky++) {
            #pragma unroll
            for (int ci = 0; ci < 16; ci++) {
                // x=px2..px2+3 <-> global gx0-1..gx0+2, both loads 8B-aligned
                const float2 a = *(const float2*)&s_h[ci][py + ky][px2];
                const float2 c = *(const float2*)&s_h[ci][py + ky][px2 + 2];
                const int wi = ci * 9 + ky * 3;
                float wy0 = c_w2[wbase_y + wi + 0];
                float wy1 = c_w2[wbase_y + wi + 1];
                float wy2 = c_w2[wbase_y + wi + 2];
                float wx0 = c_w2[wbase_x + wi + 0];
                float wx1 = c_w2[wbase_x + wi + 1];
                float wx2 = c_w2[wbase_x + wi + 2];
                dy0 = fmaf(a.x, wy0, dy0); dy0 = fmaf(a.y, wy1, dy0); dy0 = fmaf(c.x, wy2, dy0);
                dy1 = fmaf(a.y, wy0, dy1); dy1 = fmaf(c.x, wy1, dy1); dy1 = fmaf(c.y, wy2, dy1);
                dx0 = fmaf(a.x, wx0, dx0); dx0 = fmaf(a.y, wx1, dx0); dx0 = fmaf(c.x, wx2, dx0);
                dx1 = fmaf(a.y, wx0, dx1); dx1 = fmaf(c.x, wx1, dx1); dx1 = fmaf(c.y, wx2, dx1);
            }
        }

        const float kyo = (float)(k / 3 - 1);
        const float kxo = (float)(k % 3 - 1);
        #pragma unroll
        for (int px = 0; px < 2; px++) {
            float dyv = px ? dy1 : dy0;
            float dxv = px ? dx1 : dx0;
            float py_ = (float)gy + kyo + dyv;
            float px_ = (float)(gx0 + px) + kxo + dxv;
            float y0f = floorf(py_), x0f = floorf(px_);
            float wy = py_ - y0f, wx = px_ - x0f;
            int y0 = (int)y0f, x0 = (int)x0f;
            int y1 = y0 + 1,   x1 = x0 + 1;
            bool vy0 = (unsigned)y0 < HH, vy1 = (unsigned)y1 < HH;
            bool vx0 = (unsigned)x0 < WW, vx1 = (unsigned)x1 < WW;
            int yc0 = min(max(y0, 0), HH - 1), yc1 = min(max(y1, 0), HH - 1);
            int xc0 = min(max(x0, 0), WW - 1), xc1 = min(max(x1, 0), WW - 1);
            const float* r0 = pimg + yc0 * WW;
            const float* r1 = pimg + yc1 * WW;
            float v00 = (vy0 && vx0) ? r0[xc0] : 0.f;
            float v01 = (vy0 && vx1) ? r0[xc1] : 0.f;
            float v10 = (vy1 && vx0) ? r1[xc0] : 0.f;
            float v11 = (vy1 && vx1) ? r1[xc1] : 0.f;
            float samp = (1.f - wy) * (1.f - wx) * v00
                       + (1.f - wy) * wx         * v01
                       + wy         * (1.f - wx) * v10
                       + wy         * wx         * v11;
            if (px) out1 = fmaf(samp, wk, out1);
            else    out0 = fmaf(samp, wk, out0);
        }
    }

    *(float2*)&out[(size_t)b * HWS + (size_t)gy * WW + gx0] = make_float2(out0, out1);
}

extern "C" void kernel_launch(void* const* d_in, const int* in_sizes, int n_in,
                              void* d_out, int out_size) {
    const float* pm25 = (const float*)d_in[0];
    const float* wind = (const float*)d_in[1];
    const float* topo = (const float*)d_in[2];

    cudaMemcpyToSymbolAsync(c_w1, d_in[3], 432  * sizeof(float), 0, cudaMemcpyDeviceToDevice);
    cudaMemcpyToSymbolAsync(c_b1, d_in[4], 16   * sizeof(float), 0, cudaMemcpyDeviceToDevice);
    cudaMemcpyToSymbolAsync(c_w2, d_in[5], 2592 * sizeof(float), 0, cudaMemcpyDeviceToDevice);
    cudaMemcpyToSymbolAsync(c_b2, d_in[6], 18   * sizeof(float), 0, cudaMemcpyDeviceToDevice);
    cudaMemcpyToSymbolAsync(c_wt, d_in[7], 9    * sizeof(float), 0, cudaMemcpyDeviceToDevice);

    float* out = (float*)d_out;
    int B = in_sizes[0] / (HH * WW);

    dim3 gridA(1, HH, B);          // one 512-px row per block, 2 px/thread
    conv1_gelu_kernel<<<gridA, 256>>>(wind, topo);

    dim3 gridB(WW / 32, HH / 16, B);   // 32x16 tile, 2 px/thread
    deform_kernel<<<gridB, 256>>>(pm25, out);
}